// round 14
// baseline (speedup 1.0000x reference)
#include <cuda_runtime.h>
#include <cstdint>

#define LEAKY 0.2f
#define B_ 4
#define H_ 4
#define N_ 4096
#define F_ 64
#define U_ 32
#define BH_ (B_*H_)
#define NB_ 1024      // value-quantized bins per (b,h)
#define NSEG_ 32      // 32 segments of 32 bins
#define ROWS_ 64      // k1 tile rows

// ---------------- scratch (device globals; no allocations) ----------------
__device__ float g_feats[BH_ * N_ * U_];     // [bh][n][u]
__device__ float g_s[BH_ * N_];              // a_self (original order)
__device__ float g_t[BH_ * N_];              // a_neigh (original order)
__device__ float g_ea[BH_ * N_];             // exp(LEAKY*s) per query
__device__ float g_eb[BH_ * N_];             // exp(s) per query
__device__ float g_tso[BH_ * N_];            // t in bucket-scatter order
__device__ float g_w1so[BH_ * N_];           // exp(t) scatter order
__device__ float g_w2so[BH_ * N_];           // exp(LEAKY*t) scatter order
__device__ int   g_perm[BH_ * N_];           // scatter order -> original index
__device__ int   g_binstart[BH_ * (NB_ + 1)];
__device__ float g_lo[BH_], g_scale[BH_];
__device__ float g_T1[BH_ * NB_ * U_];       // per-bin vec sums [bh][bin][u]
__device__ float g_T2[BH_ * NB_ * U_];
__device__ float g_O1[BH_ * NB_ * U_];       // within-segment exclusive vec prefix
__device__ float g_O2[BH_ * NB_ * U_];
__device__ float g_SegTot1[BH_ * NSEG_ * U_];// per-segment vec totals (atomic)
__device__ float g_SegTot2[BH_ * NSEG_ * U_];
__device__ float g_Seg1[BH_ * NSEG_ * U_];   // exclusive segment offsets [bh][seg][u]
__device__ float g_Seg2[BH_ * NSEG_ * U_];
__device__ float g_C1[BH_ * NB_];            // per-bin scalar sums
__device__ float g_C2[BH_ * NB_];
__device__ float g_SegC1[BH_ * NSEG_];       // per-segment scalar totals (atomic)
__device__ float g_SegC2[BH_ * NSEG_];
__device__ float g_Sb1[BH_ * NB_];           // within-segment exclusive scalar prefix
__device__ float g_Sb2[BH_ * NB_];
__device__ float g_SegSb1[BH_ * NSEG_];      // exclusive scalar segment offsets
__device__ float g_SegSb2[BH_ * NSEG_];
__device__ float g_Stot1[BH_];               // total w1 scalar
__device__ float g_Ptot1[BH_ * U_];          // total w1*feats vector

// ============================================================
// k1: 64-row tiles, 4 threads/row (8 u's each).
// grid (N/64, BH), block 256.
// ============================================================
__global__ void __launch_bounds__(256) k1_feats(
        const float* __restrict__ x,
        const float* __restrict__ kern,
        const float* __restrict__ att_s,
        const float* __restrict__ att_n) {
    __shared__ float  xs[ROWS_][F_ + 4];
    __shared__ float4 ks4[F_ * (U_ / 4)];
    __shared__ float  as_s[U_], as_n[U_];

    const int bh = blockIdx.y;
    const int b = bh / H_, h = bh % H_;
    const int tid = threadIdx.x;

    const float4* ksrc = (const float4*)(kern + (size_t)h * F_ * U_);
#pragma unroll
    for (int i = tid; i < F_ * (U_ / 4); i += 256) ks4[i] = ksrc[i];
    if (tid < U_) { as_s[tid] = att_s[h * U_ + tid]; as_n[tid] = att_n[h * U_ + tid]; }

    const int n0 = blockIdx.x * ROWS_;
    const float4* xb4 = (const float4*)(x + ((size_t)b * N_ + n0) * F_);
#pragma unroll
    for (int i = tid; i < ROWS_ * (F_ / 4); i += 256) {
        const int r = i >> 4, c = i & 15;
        *(float4*)&xs[r][c * 4] = xb4[i];
    }
    __syncthreads();

    const int row = tid >> 2;
    const int uq  = tid & 3;

    float acc[8];
#pragma unroll
    for (int i = 0; i < 8; i++) acc[i] = 0.f;

#pragma unroll 8
    for (int f = 0; f < F_; f++) {
        const float xv = xs[row][f];
        const float4 k0 = ks4[f * 8 + uq * 2];
        const float4 k1 = ks4[f * 8 + uq * 2 + 1];
        acc[0] += xv * k0.x; acc[1] += xv * k0.y;
        acc[2] += xv * k0.z; acc[3] += xv * k0.w;
        acc[4] += xv * k1.x; acc[5] += xv * k1.y;
        acc[6] += xv * k1.z; acc[7] += xv * k1.w;
    }

    const int n = n0 + row;
    float* fo = g_feats + ((size_t)bh * N_ + n) * U_ + uq * 8;
    ((float4*)fo)[0] = make_float4(acc[0], acc[1], acc[2], acc[3]);
    ((float4*)fo)[1] = make_float4(acc[4], acc[5], acc[6], acc[7]);

    float s = 0.f, t = 0.f;
#pragma unroll
    for (int i = 0; i < 8; i++) {
        s += acc[i] * as_s[uq * 8 + i];
        t += acc[i] * as_n[uq * 8 + i];
    }
    s += __shfl_xor_sync(0xffffffffu, s, 1);
    t += __shfl_xor_sync(0xffffffffu, t, 1);
    s += __shfl_xor_sync(0xffffffffu, s, 2);
    t += __shfl_xor_sync(0xffffffffu, t, 2);
    if (uq == 0) {
        g_s[bh * N_ + n]  = s;
        g_t[bh * N_ + n]  = t;
        g_ea[bh * N_ + n] = expf(LEAKY * s);
        g_eb[bh * N_ + n] = expf(s);
    }
}

// ============================================================
// k2b: bucket + scatter; also zeroes the atomic accumulators.
// grid BH, block 1024 (4 elements/thread). ~68KB dynamic smem.
// ============================================================
__global__ void __launch_bounds__(1024, 1) k2b_bucket() {
    extern __shared__ unsigned char dsm[];
    float* tso_s  = (float*)dsm;                 // N
    float* w1_s   = tso_s + N_;                  // N
    float* w2_s   = w1_s + N_;                   // N
    int*   perm_s = (int*)(w2_s + N_);           // N
    int*   cnt    = perm_s + N_;                 // NB

    __shared__ float red[64];
    __shared__ int   wsum[32];
    __shared__ float slo, shi;

    const int bh = blockIdx.x;
    const int tid = threadIdx.x;
    const int lane = tid & 31, w = tid >> 5;

    // zero atomic accumulators for this bh (runs before k3)
    g_SegTot1[bh * NSEG_ * U_ + tid] = 0.f;
    g_SegTot2[bh * NSEG_ * U_ + tid] = 0.f;
    if (tid < NSEG_) { g_SegC1[bh * NSEG_ + tid] = 0.f; g_SegC2[bh * NSEG_ + tid] = 0.f; }

    float tv[4]; int bins[4];
    float mn = 1e30f, mx = -1e30f;
#pragma unroll
    for (int e = 0; e < 4; e++) {
        tv[e] = g_t[bh * N_ + tid * 4 + e];
        mn = fminf(mn, tv[e]); mx = fmaxf(mx, tv[e]);
    }
#pragma unroll
    for (int off = 16; off >= 1; off >>= 1) {
        mn = fminf(mn, __shfl_xor_sync(0xffffffffu, mn, off));
        mx = fmaxf(mx, __shfl_xor_sync(0xffffffffu, mx, off));
    }
    if (lane == 0) { red[w] = mn; red[32 + w] = mx; }
    cnt[tid] = 0;
    __syncthreads();
    if (w == 0) {
        float m1 = red[lane], m2 = red[32 + lane];
#pragma unroll
        for (int off = 16; off >= 1; off >>= 1) {
            m1 = fminf(m1, __shfl_xor_sync(0xffffffffu, m1, off));
            m2 = fmaxf(m2, __shfl_xor_sync(0xffffffffu, m2, off));
        }
        if (lane == 0) { slo = m1; shi = m2; }
    }
    __syncthreads();
    const float lo = slo;
    const float scale = (shi > lo) ? (float)NB_ * 0.999999f / (shi - lo) : 0.f;

#pragma unroll
    for (int e = 0; e < 4; e++) {
        int bi = (int)((tv[e] - lo) * scale);
        bi = min(NB_ - 1, max(0, bi));
        bins[e] = bi;
        atomicAdd(&cnt[bi], 1);
    }
    __syncthreads();

    const int cval = cnt[tid];
    int inc = cval;
#pragma unroll
    for (int off = 1; off < 32; off <<= 1) {
        const int o = __shfl_up_sync(0xffffffffu, inc, off);
        if (lane >= off) inc += o;
    }
    if (lane == 31) wsum[w] = inc;
    __syncthreads();
    if (tid == 0) {
        int run = 0;
#pragma unroll
        for (int k = 0; k < 32; k++) { const int xk = wsum[k]; wsum[k] = run; run += xk; }
    }
    __syncthreads();
    const int ex = inc - cval + wsum[w];
    g_binstart[bh * (NB_ + 1) + tid] = ex;
    cnt[tid] = ex;
    if (tid == 0) {
        g_binstart[bh * (NB_ + 1) + NB_] = N_;
        g_lo[bh] = lo; g_scale[bh] = scale;
    }
    __syncthreads();

#pragma unroll
    for (int e = 0; e < 4; e++) {
        const int pos = atomicAdd(&cnt[bins[e]], 1);
        perm_s[pos] = tid * 4 + e;
        tso_s[pos]  = tv[e];
        w1_s[pos]   = expf(tv[e]);
        w2_s[pos]   = expf(LEAKY * tv[e]);
    }
    __syncthreads();

#pragma unroll
    for (int k = 0; k < 4; k++) {
        const int i = tid + k * 1024;
        g_tso[bh * N_ + i]  = tso_s[i];
        g_w1so[bh * N_ + i] = w1_s[i];
        g_w2so[bh * N_ + i] = w2_s[i];
        g_perm[bh * N_ + i] = perm_s[i];
    }
}

// ============================================================
// k3: per-bin sums (warp -> bin, lane -> u) + atomic segment totals.
// grid (BH, NB/8), block 256.
// ============================================================
__global__ void __launch_bounds__(256) k3_bin_sums() {
    const int bh = blockIdx.x;
    const int w = threadIdx.x >> 5, lane = threadIdx.x & 31;
    const int bin = blockIdx.y * 8 + w;

    const int js = __ldg(&g_binstart[bh * (NB_ + 1) + bin]);
    const int je = __ldg(&g_binstart[bh * (NB_ + 1) + bin + 1]);
    const float* fe = g_feats + (size_t)bh * N_ * U_;

    float a1 = 0.f, a2 = 0.f, c1 = 0.f, c2 = 0.f;
    for (int j = js; j < je; j++) {
        const float w1 = __ldg(&g_w1so[bh * N_ + j]);
        const float w2 = __ldg(&g_w2so[bh * N_ + j]);
        const int p = __ldg(&g_perm[bh * N_ + j]);
        const float v = __ldg(&fe[p * U_ + lane]);
        a1 += w1 * v; a2 += w2 * v; c1 += w1; c2 += w2;
    }
    const size_t ti = ((size_t)bh * NB_ + bin) * U_ + lane;
    g_T1[ti] = a1;
    g_T2[ti] = a2;
    const int seg = bin >> 5;
    atomicAdd(&g_SegTot1[((size_t)bh * NSEG_ + seg) * U_ + lane], a1);
    atomicAdd(&g_SegTot2[((size_t)bh * NSEG_ + seg) * U_ + lane], a2);
    if (lane == 0) {
        g_C1[bh * NB_ + bin] = c1;
        g_C2[bh * NB_ + bin] = c2;
        atomicAdd(&g_SegC1[bh * NSEG_ + seg], c1);
        atomicAdd(&g_SegC2[bh * NSEG_ + seg], c2);
    }
}

// ============================================================
// k3b v3: grid (BH, NSEG) = 512 blocks, block 1024 (warp=bin-in-seg).
// Within-segment exclusive prefix via smem (no serial global chain);
// segment offsets from SegTot (<=31 coalesced loads).
// ============================================================
__global__ void __launch_bounds__(1024, 1) k3b_scan() {
    __shared__ float s1[NSEG_ * U_], s2[NSEG_ * U_];
    const int bh = blockIdx.x;
    const int seg = blockIdx.y;
    const int lane = threadIdx.x & 31, w = threadIdx.x >> 5;
    const int bin = seg * 32 + w;

    const size_t ti = ((size_t)bh * NB_ + bin) * U_ + lane;
    const float a1 = g_T1[ti], a2 = g_T2[ti];
    s1[w * U_ + lane] = a1;
    s2[w * U_ + lane] = a2;
    __syncthreads();

    float r1 = 0.f, r2 = 0.f;
    for (int k = 0; k < w; k++) {
        r1 += s1[k * U_ + lane];
        r2 += s2[k * U_ + lane];
    }
    g_O1[ti] = r1;
    g_O2[ti] = r2;

    if (w == 31) {   // exclusive segment offsets (vector)
        float o1 = 0.f, o2 = 0.f;
        for (int s = 0; s < seg; s++) {
            o1 += g_SegTot1[((size_t)bh * NSEG_ + s) * U_ + lane];
            o2 += g_SegTot2[((size_t)bh * NSEG_ + s) * U_ + lane];
        }
        g_Seg1[((size_t)bh * NSEG_ + seg) * U_ + lane] = o1;
        g_Seg2[((size_t)bh * NSEG_ + seg) * U_ + lane] = o2;
        if (seg == NSEG_ - 1)
            g_Ptot1[bh * U_ + lane] =
                o1 + g_SegTot1[((size_t)bh * NSEG_ + seg) * U_ + lane];
    }
    if (w == 30) {   // scalar within-seg prefix + segment offsets
        const int cb = bh * NB_ + seg * 32 + lane;
        const float c1 = g_C1[cb], c2 = g_C2[cb];
        float i1 = c1, i2 = c2;
#pragma unroll
        for (int off = 1; off < 32; off <<= 1) {
            const float x1 = __shfl_up_sync(0xffffffffu, i1, off);
            const float x2 = __shfl_up_sync(0xffffffffu, i2, off);
            if (lane >= off) { i1 += x1; i2 += x2; }
        }
        g_Sb1[cb] = i1 - c1;
        g_Sb2[cb] = i2 - c2;
        if (lane == 0) {
            float oc1 = 0.f, oc2 = 0.f;
            for (int s = 0; s < seg; s++) {
                oc1 += g_SegC1[bh * NSEG_ + s];
                oc2 += g_SegC2[bh * NSEG_ + s];
            }
            g_SegSb1[bh * NSEG_ + seg] = oc1;
            g_SegSb2[bh * NSEG_ + seg] = oc2;
            if (seg == NSEG_ - 1)
                g_Stot1[bh] = oc1 + g_SegC1[bh * NSEG_ + seg];
        }
    }
}

// ============================================================
// k4: per-node combine. warp -> one n, lane -> u. Pure load/FMA.
// grid BH*N/8, block 256
// ============================================================
__global__ void __launch_bounds__(256) k4_output(
        const float* __restrict__ biases, float* __restrict__ out) {
    const int gw = blockIdx.x * 8 + (threadIdx.x >> 5);
    const int lane = threadIdx.x & 31;
    const int bh = gw >> 12;        // / N_
    const int n = gw & (N_ - 1);
    const int b = bh >> 2, h = bh & (H_ - 1);

    const float c = g_s[bh * N_ + n];
    const float th = -c;
    const float lo = __ldg(&g_lo[bh]);
    const float scale = __ldg(&g_scale[bh]);
    int bq = (int)((th - lo) * scale);
    bq = min(NB_ - 1, max(0, bq));
    const int sq = bq >> 5;

    float p1 = __ldg(&g_O1[((size_t)bh * NB_ + bq) * U_ + lane])
             + __ldg(&g_Seg1[((size_t)bh * NSEG_ + sq) * U_ + lane]);
    float p2 = __ldg(&g_O2[((size_t)bh * NB_ + bq) * U_ + lane])
             + __ldg(&g_Seg2[((size_t)bh * NSEG_ + sq) * U_ + lane]);
    float s1 = __ldg(&g_Sb1[bh * NB_ + bq]) + __ldg(&g_SegSb1[bh * NSEG_ + sq]);
    float s2 = __ldg(&g_Sb2[bh * NB_ + bq]) + __ldg(&g_SegSb2[bh * NSEG_ + sq]);

    const int js = __ldg(&g_binstart[bh * (NB_ + 1) + bq]);
    const int je = __ldg(&g_binstart[bh * (NB_ + 1) + bq + 1]);
    const float* fe = g_feats + (size_t)bh * N_ * U_;
    for (int j = js; j < je; j++) {
        const float tv = __ldg(&g_tso[bh * N_ + j]);
        if (tv < th) {
            const float w1 = __ldg(&g_w1so[bh * N_ + j]);
            const float w2 = __ldg(&g_w2so[bh * N_ + j]);
            const int p = __ldg(&g_perm[bh * N_ + j]);
            const float v = __ldg(&fe[p * U_ + lane]);
            p1 += w1 * v; p2 += w2 * v; s1 += w1; s2 += w2;
        }
    }

    const float ea = __ldg(&g_ea[bh * N_ + n]);
    const float eb = __ldg(&g_eb[bh * N_ + n]);
    const float S1t = __ldg(&g_Stot1[bh]);
    const float pt1 = __ldg(&g_Ptot1[bh * U_ + lane]);

    const float Z = ea * s2 + eb * (S1t - s1);
    const float num = ea * p2 + eb * (pt1 - p1);
    const float val = num / Z + __ldg(&biases[h * U_ + lane]);

    out[((size_t)b * N_ + n) * (H_ * U_) + h * U_ + lane] = fmaxf(val, 0.f);
}

// ============================================================
extern "C" void kernel_launch(void* const* d_in, const int* in_sizes, int n_in,
                              void* d_out, int out_size) {
    const float* x      = (const float*)d_in[0];
    const float* kern   = (const float*)d_in[1];
    const float* att_s  = (const float*)d_in[2];
    const float* att_n  = (const float*)d_in[3];
    const float* biases = (const float*)d_in[4];
    float* out = (float*)d_out;

    const int k2b_smem = (4 * N_ + NB_) * 4;   // ~69.6 KB
    cudaFuncSetAttribute(k2b_bucket, cudaFuncAttributeMaxDynamicSharedMemorySize, k2b_smem);

    k1_feats<<<dim3(N_ / ROWS_, BH_), 256>>>(x, kern, att_s, att_n);
    k2b_bucket<<<BH_, 1024, k2b_smem>>>();
    k3_bin_sums<<<dim3(BH_, NB_ / 8), 256>>>();
    k3b_scan<<<dim3(BH_, NSEG_), 1024>>>();
    k4_output<<<(BH_ * N_) / 8, 256>>>(biases, out);
}

// round 15
// speedup vs baseline: 1.0807x; 1.0807x over previous
#include <cuda_runtime.h>
#include <cstdint>

#define LEAKY 0.2f
#define B_ 4
#define H_ 4
#define N_ 4096
#define F_ 64
#define U_ 32
#define BH_ (B_*H_)
#define NB_ 1024      // value-quantized bins per (b,h)
#define NSEG_ 32      // 32 segments of 32 bins
#define ROWS_ 64      // k1 tile rows

// ---------------- scratch (device globals; no allocations) ----------------
__device__ float g_feats[BH_ * N_ * U_];     // [bh][n][u]
__device__ float g_s[BH_ * N_];              // a_self (original order)
__device__ float g_t[BH_ * N_];              // a_neigh (original order)
__device__ float g_ea[BH_ * N_];             // exp(LEAKY*s) per query
__device__ float g_eb[BH_ * N_];             // exp(s) per query
__device__ float g_tso[BH_ * N_];            // t in bucket-scatter order
__device__ float g_w1so[BH_ * N_];           // exp(t) scatter order
__device__ float g_w2so[BH_ * N_];           // exp(LEAKY*t) scatter order
__device__ int   g_perm[BH_ * N_];           // scatter order -> original index
__device__ int   g_binstart[BH_ * (NB_ + 1)];
__device__ float g_lo[BH_], g_scale[BH_];
__device__ float g_O1[BH_ * NB_ * U_];       // within-segment exclusive vec prefix
__device__ float g_O2[BH_ * NB_ * U_];
__device__ float g_SegTot1[BH_ * NSEG_ * U_];// per-segment vec totals
__device__ float g_SegTot2[BH_ * NSEG_ * U_];
__device__ float g_Seg1[BH_ * NSEG_ * U_];   // exclusive segment offsets [bh][seg][u]
__device__ float g_Seg2[BH_ * NSEG_ * U_];
__device__ float g_SegC1[BH_ * NSEG_];       // per-segment scalar totals
__device__ float g_SegC2[BH_ * NSEG_];
__device__ float g_Sb1[BH_ * NB_];           // within-segment exclusive scalar prefix
__device__ float g_Sb2[BH_ * NB_];
__device__ float g_SegSb1[BH_ * NSEG_];      // exclusive scalar segment offsets
__device__ float g_SegSb2[BH_ * NSEG_];
__device__ float g_Stot1[BH_];               // total w1 scalar
__device__ float g_Ptot1[BH_ * U_];          // total w1*feats vector

// ============================================================
// k1: 64-row tiles, 4 threads/row (8 u's each).
// grid (N/64, BH), block 256.
// ============================================================
__global__ void __launch_bounds__(256) k1_feats(
        const float* __restrict__ x,
        const float* __restrict__ kern,
        const float* __restrict__ att_s,
        const float* __restrict__ att_n) {
    __shared__ float  xs[ROWS_][F_ + 4];
    __shared__ float4 ks4[F_ * (U_ / 4)];
    __shared__ float  as_s[U_], as_n[U_];

    const int bh = blockIdx.y;
    const int b = bh / H_, h = bh % H_;
    const int tid = threadIdx.x;

    const float4* ksrc = (const float4*)(kern + (size_t)h * F_ * U_);
#pragma unroll
    for (int i = tid; i < F_ * (U_ / 4); i += 256) ks4[i] = ksrc[i];
    if (tid < U_) { as_s[tid] = att_s[h * U_ + tid]; as_n[tid] = att_n[h * U_ + tid]; }

    const int n0 = blockIdx.x * ROWS_;
    const float4* xb4 = (const float4*)(x + ((size_t)b * N_ + n0) * F_);
#pragma unroll
    for (int i = tid; i < ROWS_ * (F_ / 4); i += 256) {
        const int r = i >> 4, c = i & 15;
        *(float4*)&xs[r][c * 4] = xb4[i];
    }
    __syncthreads();

    const int row = tid >> 2;
    const int uq  = tid & 3;

    float acc[8];
#pragma unroll
    for (int i = 0; i < 8; i++) acc[i] = 0.f;

#pragma unroll 8
    for (int f = 0; f < F_; f++) {
        const float xv = xs[row][f];
        const float4 k0 = ks4[f * 8 + uq * 2];
        const float4 k1 = ks4[f * 8 + uq * 2 + 1];
        acc[0] += xv * k0.x; acc[1] += xv * k0.y;
        acc[2] += xv * k0.z; acc[3] += xv * k0.w;
        acc[4] += xv * k1.x; acc[5] += xv * k1.y;
        acc[6] += xv * k1.z; acc[7] += xv * k1.w;
    }

    const int n = n0 + row;
    float* fo = g_feats + ((size_t)bh * N_ + n) * U_ + uq * 8;
    ((float4*)fo)[0] = make_float4(acc[0], acc[1], acc[2], acc[3]);
    ((float4*)fo)[1] = make_float4(acc[4], acc[5], acc[6], acc[7]);

    float s = 0.f, t = 0.f;
#pragma unroll
    for (int i = 0; i < 8; i++) {
        s += acc[i] * as_s[uq * 8 + i];
        t += acc[i] * as_n[uq * 8 + i];
    }
    s += __shfl_xor_sync(0xffffffffu, s, 1);
    t += __shfl_xor_sync(0xffffffffu, t, 1);
    s += __shfl_xor_sync(0xffffffffu, s, 2);
    t += __shfl_xor_sync(0xffffffffu, t, 2);
    if (uq == 0) {
        g_s[bh * N_ + n]  = s;
        g_t[bh * N_ + n]  = t;
        g_ea[bh * N_ + n] = expf(LEAKY * s);
        g_eb[bh * N_ + n] = expf(s);
    }
}

// ============================================================
// k2b: bucket + scatter. grid BH, block 1024. ~68KB dynamic smem.
// ============================================================
__global__ void __launch_bounds__(1024, 1) k2b_bucket() {
    extern __shared__ unsigned char dsm[];
    float* tso_s  = (float*)dsm;                 // N
    float* w1_s   = tso_s + N_;                  // N
    float* w2_s   = w1_s + N_;                   // N
    int*   perm_s = (int*)(w2_s + N_);           // N
    int*   cnt    = perm_s + N_;                 // NB

    __shared__ float red[64];
    __shared__ int   wsum[32];
    __shared__ float slo, shi;

    const int bh = blockIdx.x;
    const int tid = threadIdx.x;
    const int lane = tid & 31, w = tid >> 5;

    float tv[4]; int bins[4];
    float mn = 1e30f, mx = -1e30f;
#pragma unroll
    for (int e = 0; e < 4; e++) {
        tv[e] = g_t[bh * N_ + tid * 4 + e];
        mn = fminf(mn, tv[e]); mx = fmaxf(mx, tv[e]);
    }
#pragma unroll
    for (int off = 16; off >= 1; off >>= 1) {
        mn = fminf(mn, __shfl_xor_sync(0xffffffffu, mn, off));
        mx = fmaxf(mx, __shfl_xor_sync(0xffffffffu, mx, off));
    }
    if (lane == 0) { red[w] = mn; red[32 + w] = mx; }
    cnt[tid] = 0;
    __syncthreads();
    if (w == 0) {
        float m1 = red[lane], m2 = red[32 + lane];
#pragma unroll
        for (int off = 16; off >= 1; off >>= 1) {
            m1 = fminf(m1, __shfl_xor_sync(0xffffffffu, m1, off));
            m2 = fmaxf(m2, __shfl_xor_sync(0xffffffffu, m2, off));
        }
        if (lane == 0) { slo = m1; shi = m2; }
    }
    __syncthreads();
    const float lo = slo;
    const float scale = (shi > lo) ? (float)NB_ * 0.999999f / (shi - lo) : 0.f;

#pragma unroll
    for (int e = 0; e < 4; e++) {
        int bi = (int)((tv[e] - lo) * scale);
        bi = min(NB_ - 1, max(0, bi));
        bins[e] = bi;
        atomicAdd(&cnt[bi], 1);
    }
    __syncthreads();

    const int cval = cnt[tid];
    int inc = cval;
#pragma unroll
    for (int off = 1; off < 32; off <<= 1) {
        const int o = __shfl_up_sync(0xffffffffu, inc, off);
        if (lane >= off) inc += o;
    }
    if (lane == 31) wsum[w] = inc;
    __syncthreads();
    if (tid == 0) {
        int run = 0;
#pragma unroll
        for (int k = 0; k < 32; k++) { const int xk = wsum[k]; wsum[k] = run; run += xk; }
    }
    __syncthreads();
    const int ex = inc - cval + wsum[w];
    g_binstart[bh * (NB_ + 1) + tid] = ex;
    cnt[tid] = ex;
    if (tid == 0) {
        g_binstart[bh * (NB_ + 1) + NB_] = N_;
        g_lo[bh] = lo; g_scale[bh] = scale;
    }
    __syncthreads();

#pragma unroll
    for (int e = 0; e < 4; e++) {
        const int pos = atomicAdd(&cnt[bins[e]], 1);
        perm_s[pos] = tid * 4 + e;
        tso_s[pos]  = tv[e];
        w1_s[pos]   = expf(tv[e]);
        w2_s[pos]   = expf(LEAKY * tv[e]);
    }
    __syncthreads();

#pragma unroll
    for (int k = 0; k < 4; k++) {
        const int i = tid + k * 1024;
        g_tso[bh * N_ + i]  = tso_s[i];
        g_w1so[bh * N_ + i] = w1_s[i];
        g_w2so[bh * N_ + i] = w2_s[i];
        g_perm[bh * N_ + i] = perm_s[i];
    }
}

// ============================================================
// k3f: fused bin sums + within-segment prefix (no T round trip).
// grid (BH, NSEG) = 512 blocks, block 1024; warp = bin-in-seg, lane = u.
// ============================================================
__global__ void __launch_bounds__(1024, 1) k3_fused() {
    __shared__ float s1[NSEG_ * U_], s2[NSEG_ * U_];
    __shared__ float sc1[NSEG_], sc2[NSEG_];
    const int bh = blockIdx.x;
    const int seg = blockIdx.y;
    const int lane = threadIdx.x & 31, w = threadIdx.x >> 5;
    const int bin = seg * 32 + w;

    const int js = __ldg(&g_binstart[bh * (NB_ + 1) + bin]);
    const int je = __ldg(&g_binstart[bh * (NB_ + 1) + bin + 1]);
    const float* fe = g_feats + (size_t)bh * N_ * U_;

    float a1 = 0.f, a2 = 0.f, c1 = 0.f, c2 = 0.f;
    for (int j = js; j < je; j++) {
        const float w1 = __ldg(&g_w1so[bh * N_ + j]);
        const float w2 = __ldg(&g_w2so[bh * N_ + j]);
        const int p = __ldg(&g_perm[bh * N_ + j]);
        const float v = __ldg(&fe[p * U_ + lane]);
        a1 += w1 * v; a2 += w2 * v; c1 += w1; c2 += w2;
    }
    s1[w * U_ + lane] = a1;
    s2[w * U_ + lane] = a2;
    if (lane == 0) { sc1[w] = c1; sc2[w] = c2; }
    __syncthreads();

    // within-segment exclusive vector prefix from smem
    float r1 = 0.f, r2 = 0.f;
    for (int k = 0; k < w; k++) {
        r1 += s1[k * U_ + lane];
        r2 += s2[k * U_ + lane];
    }
    const size_t ti = ((size_t)bh * NB_ + bin) * U_ + lane;
    g_O1[ti] = r1;
    g_O2[ti] = r2;
    if (w == 31) {
        g_SegTot1[((size_t)bh * NSEG_ + seg) * U_ + lane] = r1 + a1;
        g_SegTot2[((size_t)bh * NSEG_ + seg) * U_ + lane] = r2 + a2;
    }

    // scalar within-segment exclusive prefix (warp 0, lane = bin-in-seg)
    if (w == 0) {
        const float b1 = sc1[lane], b2 = sc2[lane];
        float i1 = b1, i2 = b2;
#pragma unroll
        for (int off = 1; off < 32; off <<= 1) {
            const float x1 = __shfl_up_sync(0xffffffffu, i1, off);
            const float x2 = __shfl_up_sync(0xffffffffu, i2, off);
            if (lane >= off) { i1 += x1; i2 += x2; }
        }
        const int cb = bh * NB_ + seg * 32 + lane;
        g_Sb1[cb] = i1 - b1;
        g_Sb2[cb] = i2 - b2;
        if (lane == 31) {
            g_SegC1[bh * NSEG_ + seg] = i1;   // inclusive segment totals
            g_SegC2[bh * NSEG_ + seg] = i2;
        }
    }
}

// ============================================================
// kseg: segment-level exclusive offsets + grand totals.
// grid BH, block 1024 (w = seg, lane = u).
// ============================================================
__global__ void __launch_bounds__(1024, 1) kseg_scan() {
    __shared__ float m1[NSEG_ * U_], m2[NSEG_ * U_];
    const int bh = blockIdx.x;
    const int tid = threadIdx.x;
    const int lane = tid & 31, w = tid >> 5;

    m1[tid] = g_SegTot1[(size_t)bh * NSEG_ * U_ + tid];
    m2[tid] = g_SegTot2[(size_t)bh * NSEG_ * U_ + tid];
    __syncthreads();

    float o1 = 0.f, o2 = 0.f;
    for (int s = 0; s < w; s++) {
        o1 += m1[s * U_ + lane];
        o2 += m2[s * U_ + lane];
    }
    g_Seg1[(size_t)bh * NSEG_ * U_ + tid] = o1;
    g_Seg2[(size_t)bh * NSEG_ * U_ + tid] = o2;
    if (w == 31) g_Ptot1[bh * U_ + lane] = o1 + m1[31 * U_ + lane];

    if (w == 0) {   // scalar segment offsets via shfl scan (lane = seg)
        const float c1 = g_SegC1[bh * NSEG_ + lane];
        const float c2 = g_SegC2[bh * NSEG_ + lane];
        float i1 = c1, i2 = c2;
#pragma unroll
        for (int off = 1; off < 32; off <<= 1) {
            const float x1 = __shfl_up_sync(0xffffffffu, i1, off);
            const float x2 = __shfl_up_sync(0xffffffffu, i2, off);
            if (lane >= off) { i1 += x1; i2 += x2; }
        }
        g_SegSb1[bh * NSEG_ + lane] = i1 - c1;
        g_SegSb2[bh * NSEG_ + lane] = i2 - c2;
        if (lane == 31) g_Stot1[bh] = i1;
    }
}

// ============================================================
// k4: per-node combine. warp -> one n, lane -> u. Pure load/FMA.
// grid BH*N/8, block 256
// ============================================================
__global__ void __launch_bounds__(256) k4_output(
        const float* __restrict__ biases, float* __restrict__ out) {
    const int gw = blockIdx.x * 8 + (threadIdx.x >> 5);
    const int lane = threadIdx.x & 31;
    const int bh = gw >> 12;        // / N_
    const int n = gw & (N_ - 1);
    const int b = bh >> 2, h = bh & (H_ - 1);

    const float c = g_s[bh * N_ + n];
    const float th = -c;
    const float lo = __ldg(&g_lo[bh]);
    const float scale = __ldg(&g_scale[bh]);
    int bq = (int)((th - lo) * scale);
    bq = min(NB_ - 1, max(0, bq));
    const int sq = bq >> 5;

    float p1 = __ldg(&g_O1[((size_t)bh * NB_ + bq) * U_ + lane])
             + __ldg(&g_Seg1[((size_t)bh * NSEG_ + sq) * U_ + lane]);
    float p2 = __ldg(&g_O2[((size_t)bh * NB_ + bq) * U_ + lane])
             + __ldg(&g_Seg2[((size_t)bh * NSEG_ + sq) * U_ + lane]);
    float s1 = __ldg(&g_Sb1[bh * NB_ + bq]) + __ldg(&g_SegSb1[bh * NSEG_ + sq]);
    float s2 = __ldg(&g_Sb2[bh * NB_ + bq]) + __ldg(&g_SegSb2[bh * NSEG_ + sq]);

    const int js = __ldg(&g_binstart[bh * (NB_ + 1) + bq]);
    const int je = __ldg(&g_binstart[bh * (NB_ + 1) + bq + 1]);
    const float* fe = g_feats + (size_t)bh * N_ * U_;
    for (int j = js; j < je; j++) {
        const float tv = __ldg(&g_tso[bh * N_ + j]);
        if (tv < th) {
            const float w1 = __ldg(&g_w1so[bh * N_ + j]);
            const float w2 = __ldg(&g_w2so[bh * N_ + j]);
            const int p = __ldg(&g_perm[bh * N_ + j]);
            const float v = __ldg(&fe[p * U_ + lane]);
            p1 += w1 * v; p2 += w2 * v; s1 += w1; s2 += w2;
        }
    }

    const float ea = __ldg(&g_ea[bh * N_ + n]);
    const float eb = __ldg(&g_eb[bh * N_ + n]);
    const float S1t = __ldg(&g_Stot1[bh]);
    const float pt1 = __ldg(&g_Ptot1[bh * U_ + lane]);

    const float Z = ea * s2 + eb * (S1t - s1);
    const float num = ea * p2 + eb * (pt1 - p1);
    const float val = num / Z + __ldg(&biases[h * U_ + lane]);

    out[((size_t)b * N_ + n) * (H_ * U_) + h * U_ + lane] = fmaxf(val, 0.f);
}

// ============================================================
extern "C" void kernel_launch(void* const* d_in, const int* in_sizes, int n_in,
                              void* d_out, int out_size) {
    const float* x      = (const float*)d_in[0];
    const float* kern   = (const float*)d_in[1];
    const float* att_s  = (const float*)d_in[2];
    const float* att_n  = (const float*)d_in[3];
    const float* biases = (const float*)d_in[4];
    float* out = (float*)d_out;

    const int k2b_smem = (4 * N_ + NB_) * 4;   // ~69.6 KB
    cudaFuncSetAttribute(k2b_bucket, cudaFuncAttributeMaxDynamicSharedMemorySize, k2b_smem);

    k1_feats<<<dim3(N_ / ROWS_, BH_), 256>>>(x, kern, att_s, att_n);
    k2b_bucket<<<BH_, 1024, k2b_smem>>>();
    k3_fused<<<dim3(BH_, NSEG_), 1024>>>();
    kseg_scan<<<BH_, 1024>>>();
    k4_output<<<(BH_ * N_) / 8, 256>>>(biases, out);
}

// round 16
// speedup vs baseline: 1.1097x; 1.0269x over previous
#include <cuda_runtime.h>
#include <cstdint>

#define LEAKY 0.2f
#define B_ 4
#define H_ 4
#define N_ 4096
#define F_ 64
#define U_ 32
#define BH_ (B_*H_)
#define NB_ 1024      // value-quantized bins per (b,h)
#define NSEG_ 32      // 32 segments of 32 bins
#define ROWS_ 64      // k1 tile rows

// ---------------- scratch (device globals; no allocations) ----------------
__device__ float g_feats[BH_ * N_ * U_];     // [bh][n][u]
__device__ float g_s[BH_ * N_];              // a_self (original order)
__device__ float g_t[BH_ * N_];              // a_neigh (original order)
__device__ float g_ea[BH_ * N_];             // exp(LEAKY*s) per query
__device__ float g_eb[BH_ * N_];             // exp(s) per query
__device__ float g_tso[BH_ * N_];            // t in bucket-scatter order
__device__ float g_w1so[BH_ * N_];           // exp(t) scatter order
__device__ float g_w2so[BH_ * N_];           // exp(LEAKY*t) scatter order
__device__ int   g_perm[BH_ * N_];           // scatter order -> original index
__device__ int   g_binstart[BH_ * (NB_ + 1)];
__device__ float g_lo[BH_], g_scale[BH_];
__device__ float g_O1[BH_ * NB_ * U_];       // within-segment exclusive vec prefix
__device__ float g_O2[BH_ * NB_ * U_];
__device__ float g_Seg1[BH_ * NSEG_ * U_];   // exclusive segment offsets (atomic-built)
__device__ float g_Seg2[BH_ * NSEG_ * U_];
__device__ float g_Sb1[BH_ * NB_];           // within-segment exclusive scalar prefix
__device__ float g_Sb2[BH_ * NB_];
__device__ float g_SegSb1[BH_ * NSEG_];      // exclusive scalar segment offsets (atomic)
__device__ float g_SegSb2[BH_ * NSEG_];
__device__ float g_Stot1[BH_];               // total w1 scalar (atomic)
__device__ float g_Ptot1[BH_ * U_];          // total w1*feats vector (atomic)

// ============================================================
// k1: 64-row tiles, 4 threads/row (8 u's each).
// grid (N/64, BH), block 256.
// ============================================================
__global__ void __launch_bounds__(256) k1_feats(
        const float* __restrict__ x,
        const float* __restrict__ kern,
        const float* __restrict__ att_s,
        const float* __restrict__ att_n) {
    __shared__ float  xs[ROWS_][F_ + 4];
    __shared__ float4 ks4[F_ * (U_ / 4)];
    __shared__ float  as_s[U_], as_n[U_];

    const int bh = blockIdx.y;
    const int b = bh / H_, h = bh % H_;
    const int tid = threadIdx.x;

    const float4* ksrc = (const float4*)(kern + (size_t)h * F_ * U_);
#pragma unroll
    for (int i = tid; i < F_ * (U_ / 4); i += 256) ks4[i] = ksrc[i];
    if (tid < U_) { as_s[tid] = att_s[h * U_ + tid]; as_n[tid] = att_n[h * U_ + tid]; }

    const int n0 = blockIdx.x * ROWS_;
    const float4* xb4 = (const float4*)(x + ((size_t)b * N_ + n0) * F_);
#pragma unroll
    for (int i = tid; i < ROWS_ * (F_ / 4); i += 256) {
        const int r = i >> 4, c = i & 15;
        *(float4*)&xs[r][c * 4] = xb4[i];
    }
    __syncthreads();

    const int row = tid >> 2;
    const int uq  = tid & 3;

    float acc[8];
#pragma unroll
    for (int i = 0; i < 8; i++) acc[i] = 0.f;

#pragma unroll 8
    for (int f = 0; f < F_; f++) {
        const float xv = xs[row][f];
        const float4 k0 = ks4[f * 8 + uq * 2];
        const float4 k1 = ks4[f * 8 + uq * 2 + 1];
        acc[0] += xv * k0.x; acc[1] += xv * k0.y;
        acc[2] += xv * k0.z; acc[3] += xv * k0.w;
        acc[4] += xv * k1.x; acc[5] += xv * k1.y;
        acc[6] += xv * k1.z; acc[7] += xv * k1.w;
    }

    const int n = n0 + row;
    float* fo = g_feats + ((size_t)bh * N_ + n) * U_ + uq * 8;
    ((float4*)fo)[0] = make_float4(acc[0], acc[1], acc[2], acc[3]);
    ((float4*)fo)[1] = make_float4(acc[4], acc[5], acc[6], acc[7]);

    float s = 0.f, t = 0.f;
#pragma unroll
    for (int i = 0; i < 8; i++) {
        s += acc[i] * as_s[uq * 8 + i];
        t += acc[i] * as_n[uq * 8 + i];
    }
    s += __shfl_xor_sync(0xffffffffu, s, 1);
    t += __shfl_xor_sync(0xffffffffu, t, 1);
    s += __shfl_xor_sync(0xffffffffu, s, 2);
    t += __shfl_xor_sync(0xffffffffu, t, 2);
    if (uq == 0) {
        g_s[bh * N_ + n]  = s;
        g_t[bh * N_ + n]  = t;
        g_ea[bh * N_ + n] = expf(LEAKY * s);
        g_eb[bh * N_ + n] = expf(s);
    }
}

// ============================================================
// k2b: bucket + scatter; zeroes the atomic accumulators.
// grid BH, block 1024. ~68KB dynamic smem.
// ============================================================
__global__ void __launch_bounds__(1024, 1) k2b_bucket() {
    extern __shared__ unsigned char dsm[];
    float* tso_s  = (float*)dsm;                 // N
    float* w1_s   = tso_s + N_;                  // N
    float* w2_s   = w1_s + N_;                   // N
    int*   perm_s = (int*)(w2_s + N_);           // N
    int*   cnt    = perm_s + N_;                 // NB

    __shared__ float red[64];
    __shared__ int   wsum[32];
    __shared__ float slo, shi;

    const int bh = blockIdx.x;
    const int tid = threadIdx.x;
    const int lane = tid & 31, w = tid >> 5;

    // zero atomic accumulators for this bh (runs before k3f)
    g_Seg1[(size_t)bh * NSEG_ * U_ + tid] = 0.f;    // NSEG*U == 1024
    g_Seg2[(size_t)bh * NSEG_ * U_ + tid] = 0.f;
    if (tid < NSEG_) { g_SegSb1[bh * NSEG_ + tid] = 0.f; g_SegSb2[bh * NSEG_ + tid] = 0.f; }
    if (tid < U_) g_Ptot1[bh * U_ + tid] = 0.f;
    if (tid == 0) g_Stot1[bh] = 0.f;

    float tv[4]; int bins[4];
    float mn = 1e30f, mx = -1e30f;
#pragma unroll
    for (int e = 0; e < 4; e++) {
        tv[e] = g_t[bh * N_ + tid * 4 + e];
        mn = fminf(mn, tv[e]); mx = fmaxf(mx, tv[e]);
    }
#pragma unroll
    for (int off = 16; off >= 1; off >>= 1) {
        mn = fminf(mn, __shfl_xor_sync(0xffffffffu, mn, off));
        mx = fmaxf(mx, __shfl_xor_sync(0xffffffffu, mx, off));
    }
    if (lane == 0) { red[w] = mn; red[32 + w] = mx; }
    cnt[tid] = 0;
    __syncthreads();
    if (w == 0) {
        float m1 = red[lane], m2 = red[32 + lane];
#pragma unroll
        for (int off = 16; off >= 1; off >>= 1) {
            m1 = fminf(m1, __shfl_xor_sync(0xffffffffu, m1, off));
            m2 = fmaxf(m2, __shfl_xor_sync(0xffffffffu, m2, off));
        }
        if (lane == 0) { slo = m1; shi = m2; }
    }
    __syncthreads();
    const float lo = slo;
    const float scale = (shi > lo) ? (float)NB_ * 0.999999f / (shi - lo) : 0.f;

#pragma unroll
    for (int e = 0; e < 4; e++) {
        int bi = (int)((tv[e] - lo) * scale);
        bi = min(NB_ - 1, max(0, bi));
        bins[e] = bi;
        atomicAdd(&cnt[bi], 1);
    }
    __syncthreads();

    const int cval = cnt[tid];
    int inc = cval;
#pragma unroll
    for (int off = 1; off < 32; off <<= 1) {
        const int o = __shfl_up_sync(0xffffffffu, inc, off);
        if (lane >= off) inc += o;
    }
    if (lane == 31) wsum[w] = inc;
    __syncthreads();
    if (tid == 0) {
        int run = 0;
#pragma unroll
        for (int k = 0; k < 32; k++) { const int xk = wsum[k]; wsum[k] = run; run += xk; }
    }
    __syncthreads();
    const int ex = inc - cval + wsum[w];
    g_binstart[bh * (NB_ + 1) + tid] = ex;
    cnt[tid] = ex;
    if (tid == 0) {
        g_binstart[bh * (NB_ + 1) + NB_] = N_;
        g_lo[bh] = lo; g_scale[bh] = scale;
    }
    __syncthreads();

#pragma unroll
    for (int e = 0; e < 4; e++) {
        const int pos = atomicAdd(&cnt[bins[e]], 1);
        perm_s[pos] = tid * 4 + e;
        tso_s[pos]  = tv[e];
        w1_s[pos]   = expf(tv[e]);
        w2_s[pos]   = expf(LEAKY * tv[e]);
    }
    __syncthreads();

#pragma unroll
    for (int k = 0; k < 4; k++) {
        const int i = tid + k * 1024;
        g_tso[bh * N_ + i]  = tso_s[i];
        g_w1so[bh * N_ + i] = w1_s[i];
        g_w2so[bh * N_ + i] = w2_s[i];
        g_perm[bh * N_ + i] = perm_s[i];
    }
}

// ============================================================
// k3f: fused bin sums + within-segment prefix + atomic
// suffix-propagation of segment totals (kseg eliminated).
// grid (BH, NSEG) = 512 blocks, block 1024; warp = bin-in-seg, lane = u.
// ============================================================
__global__ void __launch_bounds__(1024, 1) k3_fused() {
    __shared__ float s1[NSEG_ * U_], s2[NSEG_ * U_];
    __shared__ float sc1[NSEG_], sc2[NSEG_];
    const int bh = blockIdx.x;
    const int seg = blockIdx.y;
    const int lane = threadIdx.x & 31, w = threadIdx.x >> 5;
    const int bin = seg * 32 + w;

    const int js = __ldg(&g_binstart[bh * (NB_ + 1) + bin]);
    const int je = __ldg(&g_binstart[bh * (NB_ + 1) + bin + 1]);
    const float* fe = g_feats + (size_t)bh * N_ * U_;

    float a1 = 0.f, a2 = 0.f, c1 = 0.f, c2 = 0.f;
    for (int j = js; j < je; j++) {
        const float w1 = __ldg(&g_w1so[bh * N_ + j]);
        const float w2 = __ldg(&g_w2so[bh * N_ + j]);
        const int p = __ldg(&g_perm[bh * N_ + j]);
        const float v = __ldg(&fe[p * U_ + lane]);
        a1 += w1 * v; a2 += w2 * v; c1 += w1; c2 += w2;
    }
    s1[w * U_ + lane] = a1;
    s2[w * U_ + lane] = a2;
    if (lane == 0) { sc1[w] = c1; sc2[w] = c2; }
    __syncthreads();

    // within-segment exclusive vector prefix from smem
    float r1 = 0.f, r2 = 0.f;
    for (int k = 0; k < w; k++) {
        r1 += s1[k * U_ + lane];
        r2 += s2[k * U_ + lane];
    }
    const size_t ti = ((size_t)bh * NB_ + bin) * U_ + lane;
    g_O1[ti] = r1;
    g_O2[ti] = r2;

    if (w == 31) {
        // segment totals -> atomically propagate into all later segments
        const float tot1 = r1 + a1, tot2 = r2 + a2;
        atomicAdd(&g_Ptot1[bh * U_ + lane], tot1);
        for (int s = seg + 1; s < NSEG_; s++) {
            atomicAdd(&g_Seg1[((size_t)bh * NSEG_ + s) * U_ + lane], tot1);
            atomicAdd(&g_Seg2[((size_t)bh * NSEG_ + s) * U_ + lane], tot2);
        }
    }

    // scalar within-segment exclusive prefix (warp 0, lane = bin-in-seg)
    if (w == 0) {
        const float b1 = sc1[lane], b2 = sc2[lane];
        float i1 = b1, i2 = b2;
#pragma unroll
        for (int off = 1; off < 32; off <<= 1) {
            const float x1 = __shfl_up_sync(0xffffffffu, i1, off);
            const float x2 = __shfl_up_sync(0xffffffffu, i2, off);
            if (lane >= off) { i1 += x1; i2 += x2; }
        }
        const int cb = bh * NB_ + seg * 32 + lane;
        g_Sb1[cb] = i1 - b1;
        g_Sb2[cb] = i2 - b2;
        // scalar segment totals -> propagate to later segments (lane = target seg)
        const float ct1 = __shfl_sync(0xffffffffu, i1, 31);
        const float ct2 = __shfl_sync(0xffffffffu, i2, 31);
        if (lane > seg) {
            atomicAdd(&g_SegSb1[bh * NSEG_ + lane], ct1);
            atomicAdd(&g_SegSb2[bh * NSEG_ + lane], ct2);
        }
        if (lane == 31) atomicAdd(&g_Stot1[bh], ct1);
    }
}

// ============================================================
// k4: per-node combine. warp -> one n, lane -> u. Pure load/FMA.
// grid BH*N/8, block 256
// ============================================================
__global__ void __launch_bounds__(256) k4_output(
        const float* __restrict__ biases, float* __restrict__ out) {
    const int gw = blockIdx.x * 8 + (threadIdx.x >> 5);
    const int lane = threadIdx.x & 31;
    const int bh = gw >> 12;        // / N_
    const int n = gw & (N_ - 1);
    const int b = bh >> 2, h = bh & (H_ - 1);

    const float c = g_s[bh * N_ + n];
    const float th = -c;
    const float lo = __ldg(&g_lo[bh]);
    const float scale = __ldg(&g_scale[bh]);
    int bq = (int)((th - lo) * scale);
    bq = min(NB_ - 1, max(0, bq));
    const int sq = bq >> 5;

    float p1 = __ldg(&g_O1[((size_t)bh * NB_ + bq) * U_ + lane])
             + __ldg(&g_Seg1[((size_t)bh * NSEG_ + sq) * U_ + lane]);
    float p2 = __ldg(&g_O2[((size_t)bh * NB_ + bq) * U_ + lane])
             + __ldg(&g_Seg2[((size_t)bh * NSEG_ + sq) * U_ + lane]);
    float s1 = __ldg(&g_Sb1[bh * NB_ + bq]) + __ldg(&g_SegSb1[bh * NSEG_ + sq]);
    float s2 = __ldg(&g_Sb2[bh * NB_ + bq]) + __ldg(&g_SegSb2[bh * NSEG_ + sq]);

    const int js = __ldg(&g_binstart[bh * (NB_ + 1) + bq]);
    const int je = __ldg(&g_binstart[bh * (NB_ + 1) + bq + 1]);
    const float* fe = g_feats + (size_t)bh * N_ * U_;
    for (int j = js; j < je; j++) {
        const float tv = __ldg(&g_tso[bh * N_ + j]);
        if (tv < th) {
            const float w1 = __ldg(&g_w1so[bh * N_ + j]);
            const float w2 = __ldg(&g_w2so[bh * N_ + j]);
            const int p = __ldg(&g_perm[bh * N_ + j]);
            const float v = __ldg(&fe[p * U_ + lane]);
            p1 += w1 * v; p2 += w2 * v; s1 += w1; s2 += w2;
        }
    }

    const float ea = __ldg(&g_ea[bh * N_ + n]);
    const float eb = __ldg(&g_eb[bh * N_ + n]);
    const float S1t = __ldg(&g_Stot1[bh]);
    const float pt1 = __ldg(&g_Ptot1[bh * U_ + lane]);

    const float Z = ea * s2 + eb * (S1t - s1);
    const float num = ea * p2 + eb * (pt1 - p1);
    const float val = num / Z + __ldg(&biases[h * U_ + lane]);

    out[((size_t)b * N_ + n) * (H_ * U_) + h * U_ + lane] = fmaxf(val, 0.f);
}

// ============================================================
extern "C" void kernel_launch(void* const* d_in, const int* in_sizes, int n_in,
                              void* d_out, int out_size) {
    const float* x      = (const float*)d_in[0];
    const float* kern   = (const float*)d_in[1];
    const float* att_s  = (const float*)d_in[2];
    const float* att_n  = (const float*)d_in[3];
    const float* biases = (const float*)d_in[4];
    float* out = (float*)d_out;

    const int k2b_smem = (4 * N_ + NB_) * 4;   // ~69.6 KB
    cudaFuncSetAttribute(k2b_bucket, cudaFuncAttributeMaxDynamicSharedMemorySize, k2b_smem);

    k1_feats<<<dim3(N_ / ROWS_, BH_), 256>>>(x, kern, att_s, att_n);
    k2b_bucket<<<BH_, 1024, k2b_smem>>>();
    k3_fused<<<dim3(BH_, NSEG_), 1024>>>();
    k4_output<<<(BH_ * N_) / 8, 256>>>(biases, out);
}